// round 5
// baseline (speedup 1.0000x reference)
#include <cuda_runtime.h>
#include <math.h>

#define S_LEN 3744
#define DIM 1536
#define NH 12
#define HD 128
#define HH 26
#define WW 48
#define EPSN 1e-6f

// scratch (allocation-free rule: __device__ globals)
__device__ float g_q[S_LEN * DIM];
__device__ float g_k[S_LEN * DIM];
__device__ float g_v[S_LEN * DIM];
__device__ float g_o[S_LEN * DIM];
__device__ float g_rq[S_LEN];
__device__ float g_rk[S_LEN];

// ---------------------------------------------------------------------------
// GEMM: C[M,N] = A[M,K] @ B[N,K]^T + bias[N]
// 128x128 tile, BK=16, 256 threads, 8x8 micro-tile.
// ---------------------------------------------------------------------------
__global__ __launch_bounds__(256, 2) void gemm_nt_bias(
    const float* __restrict__ A, const float* __restrict__ Bw,
    const float* __restrict__ bias, float* __restrict__ C,
    int M, int N, int K)
{
    __shared__ float As[16][128];
    __shared__ float Bs[16][128];
    const int tid = threadIdx.x;
    const int bm = blockIdx.y * 128;
    const int bn = blockIdx.x * 128;
    const int i0 = (tid >> 4) * 8, j0 = (tid & 15) * 8;

    float acc[8][8];
#pragma unroll
    for (int a = 0; a < 8; a++)
#pragma unroll
        for (int b = 0; b < 8; b++) acc[a][b] = 0.f;

    const int r = tid & 127;
    const int kqb = tid >> 7;  // 0 or 1
    const float* Arow = A + (size_t)(bm + r) * K;
    const float* Brow = Bw + (size_t)(bn + r) * K;
    const bool aval = (bm + r) < M;

    for (int kt = 0; kt < K; kt += 16) {
        float4 a0, a1;
        if (aval) {
            a0 = *(const float4*)(Arow + kt + kqb * 4);
            a1 = *(const float4*)(Arow + kt + (kqb + 2) * 4);
        } else {
            a0 = make_float4(0.f, 0.f, 0.f, 0.f);
            a1 = a0;
        }
        float4 b0 = *(const float4*)(Brow + kt + kqb * 4);
        float4 b1 = *(const float4*)(Brow + kt + (kqb + 2) * 4);

        __syncthreads();
        As[kqb * 4 + 0][r] = a0.x; As[kqb * 4 + 1][r] = a0.y;
        As[kqb * 4 + 2][r] = a0.z; As[kqb * 4 + 3][r] = a0.w;
        As[(kqb + 2) * 4 + 0][r] = a1.x; As[(kqb + 2) * 4 + 1][r] = a1.y;
        As[(kqb + 2) * 4 + 2][r] = a1.z; As[(kqb + 2) * 4 + 3][r] = a1.w;
        Bs[kqb * 4 + 0][r] = b0.x; Bs[kqb * 4 + 1][r] = b0.y;
        Bs[kqb * 4 + 2][r] = b0.z; Bs[kqb * 4 + 3][r] = b0.w;
        Bs[(kqb + 2) * 4 + 0][r] = b1.x; Bs[(kqb + 2) * 4 + 1][r] = b1.y;
        Bs[(kqb + 2) * 4 + 2][r] = b1.z; Bs[(kqb + 2) * 4 + 3][r] = b1.w;
        __syncthreads();

#pragma unroll
        for (int kk = 0; kk < 16; kk++) {
            float4 qa0 = *(const float4*)&As[kk][i0];
            float4 qa1 = *(const float4*)&As[kk][i0 + 4];
            float4 qb0 = *(const float4*)&Bs[kk][j0];
            float4 qb1 = *(const float4*)&Bs[kk][j0 + 4];
            float av[8] = {qa0.x, qa0.y, qa0.z, qa0.w, qa1.x, qa1.y, qa1.z, qa1.w};
            float bv[8] = {qb0.x, qb0.y, qb0.z, qb0.w, qb1.x, qb1.y, qb1.z, qb1.w};
#pragma unroll
            for (int ii = 0; ii < 8; ii++)
#pragma unroll
                for (int jj = 0; jj < 8; jj++)
                    acc[ii][jj] = fmaf(av[ii], bv[jj], acc[ii][jj]);
        }
    }

#pragma unroll
    for (int ii = 0; ii < 8; ii++) {
        int m = bm + i0 + ii;
        if (m < M) {
            float* Crow = C + (size_t)m * N + bn + j0;
            const float* brow = bias + bn + j0;
#pragma unroll
            for (int jj = 0; jj < 8; jj++)
                Crow[jj] = acc[ii][jj] + brow[jj];
        }
    }
}

// ---------------------------------------------------------------------------
// Pass 1: per-row inverse RMS of q and k (over full DIM).
// ---------------------------------------------------------------------------
__global__ __launch_bounds__(256) void rms_kernel(
    const float* __restrict__ q, const float* __restrict__ k,
    float* __restrict__ rqv, float* __restrict__ rkv)
{
    const int s = blockIdx.x;
    const int tid = threadIdx.x;
    const float* qr = q + (size_t)s * DIM;
    const float* kr = k + (size_t)s * DIM;

    float sq = 0.f, sk = 0.f;
    for (int i = tid; i < DIM; i += 256) {
        float a = qr[i]; sq = fmaf(a, a, sq);
        float b = kr[i]; sk = fmaf(b, b, sk);
    }
    __shared__ float bq_[256], bk_[256];
    bq_[tid] = sq; bk_[tid] = sk;
    __syncthreads();
    for (int off = 128; off > 0; off >>= 1) {
        if (tid < off) { bq_[tid] += bq_[tid + off]; bk_[tid] += bk_[tid + off]; }
        __syncthreads();
    }
    if (tid == 0) {
        rqv[s] = rsqrtf(bq_[0] * (1.0f / DIM) + EPSN);
        rkv[s] = rsqrtf(bk_[0] * (1.0f / DIM) + EPSN);
    }
}

// ---------------------------------------------------------------------------
// Pass 2: apply RMSNorm gain + 3D RoPE, angles computed from first principles
// (matches numpy: inv = 10000^(-2j/dim), ang = pos * inv; splits 22/21/21
// over the f/h/w axes, dims 44/42/42). Double precision for the table math.
// ---------------------------------------------------------------------------
__global__ __launch_bounds__(256) void rope_kernel(
    float* __restrict__ q, float* __restrict__ k,
    const float* __restrict__ gq, const float* __restrict__ gk,
    const float* __restrict__ rqv, const float* __restrict__ rkv)
{
    const int s = blockIdx.x;
    const int tid = threadIdx.x;
    float* qr = q + (size_t)s * DIM;
    float* kr = k + (size_t)s * DIM;
    const float rq = rqv[s];
    const float rk = rkv[s];

    const int f = s / (HH * WW);
    const int rem = s - f * (HH * WW);
    const int hp = rem / WW;
    const int wp = rem - hp * WW;

#pragma unroll
    for (int u = 0; u < 3; u++) {
        int p = tid + u * 256;       // 0..767 = NH*64 pairs
        int h = p >> 6;
        int c = p & 63;
        int pos, j, dim;
        if (c < 22)      { pos = f;  j = c;      dim = 44; }
        else if (c < 43) { pos = hp; j = c - 22; dim = 42; }
        else             { pos = wp; j = c - 43; dim = 42; }
        double inv = pow(10000.0, -2.0 * (double)j / (double)dim);
        double ang = (double)pos * inv;
        double sd, cd;
        sincos(ang, &sd, &cd);
        float cs = (float)cd, sn = (float)sd;

        int base = h * HD + 2 * c;
        float q0 = qr[base] * rq * gq[base];
        float q1 = qr[base + 1] * rq * gq[base + 1];
        qr[base]     = q0 * cs - q1 * sn;
        qr[base + 1] = q0 * sn + q1 * cs;
        float k0 = kr[base] * rk * gk[base];
        float k1 = kr[base + 1] * rk * gk[base + 1];
        kr[base]     = k0 * cs - k1 * sn;
        kr[base + 1] = k0 * sn + k1 * cs;
    }
}

// ---------------------------------------------------------------------------
// Flash attention, fp32. One block per (q-tile of 128 rows, head).
// ---------------------------------------------------------------------------
#define PS_STRIDE 66
#define FLASH_SMEM_FLOATS (128 * 128 + 16 * 64 + 128 * PS_STRIDE + 64 * 128 + 3 * 128)
#define FLASH_SMEM_BYTES (FLASH_SMEM_FLOATS * 4)

__global__ __launch_bounds__(256, 1) void flash_kernel(
    const float* __restrict__ q, const float* __restrict__ k,
    const float* __restrict__ v, float* __restrict__ o,
    const int* __restrict__ seq_lens)
{
    extern __shared__ float sm[];
    float* Qs = sm;                          // [128 d][128 i]
    float* Ks = Qs + 128 * 128;              // [16 dk][64 j]
    float* Ps = Ks + 16 * 64;                // [128 i][PS_STRIDE], j in 0..63
    float* Vs = Ps + 128 * PS_STRIDE;        // [64 j][128 d]
    float* mrow = Vs + 64 * 128;             // [128]
    float* lrow = mrow + 128;                // [128]
    float* arow = lrow + 128;                // [128]

    const int tid = threadIdx.x;
    const int head = blockIdx.y;
    const int q0 = blockIdx.x * 128;
    const int seqlen = seq_lens[0];
    const int hoff = head * HD;

    {
        const int row = tid & 127;
        const int d4b = tid >> 7;
        const float* qrow = q + (size_t)(q0 + row) * DIM + hoff;
        const bool valid = (q0 + row) < S_LEN;
#pragma unroll
        for (int u = 0; u < 16; u++) {
            int d4 = d4b + u * 2;
            float4 val = valid ? *(const float4*)(qrow + d4 * 4)
                               : make_float4(0.f, 0.f, 0.f, 0.f);
            Qs[(d4 * 4 + 0) * 128 + row] = val.x;
            Qs[(d4 * 4 + 1) * 128 + row] = val.y;
            Qs[(d4 * 4 + 2) * 128 + row] = val.z;
            Qs[(d4 * 4 + 3) * 128 + row] = val.w;
        }
    }
    if (tid < 128) { mrow[tid] = -3.0e38f; lrow[tid] = 0.f; }
    __syncthreads();

    const int ig = tid >> 4, jg = tid & 15;
    const int i0 = ig * 8;
    const int d0 = jg * 8;
    const int jj0 = jg * 4;

    float acc[8][8];
#pragma unroll
    for (int a = 0; a < 8; a++)
#pragma unroll
        for (int b = 0; b < 8; b++) acc[a][b] = 0.f;

    const float scale = 0.08838834764831845f;

    const int kj = tid & 63;
    const int dk4 = tid >> 6;

    for (int kv0 = 0; kv0 < seqlen; kv0 += 64) {
        float sacc[8][4];
#pragma unroll
        for (int a = 0; a < 8; a++)
#pragma unroll
            for (int b = 0; b < 4; b++) sacc[a][b] = 0.f;

        const float* krow = k + (size_t)(kv0 + kj) * DIM + hoff;
        const bool kval = (kv0 + kj) < seqlen;

        for (int dt = 0; dt < HD; dt += 16) {
            float4 kvv = kval ? *(const float4*)(krow + dt + dk4 * 4)
                              : make_float4(0.f, 0.f, 0.f, 0.f);
            __syncthreads();
            Ks[(dk4 * 4 + 0) * 64 + kj] = kvv.x;
            Ks[(dk4 * 4 + 1) * 64 + kj] = kvv.y;
            Ks[(dk4 * 4 + 2) * 64 + kj] = kvv.z;
            Ks[(dk4 * 4 + 3) * 64 + kj] = kvv.w;
            __syncthreads();
#pragma unroll
            for (int kk = 0; kk < 16; kk++) {
                const float* qp = Qs + (dt + kk) * 128 + i0;
                float4 a0 = *(const float4*)qp;
                float4 a1 = *(const float4*)(qp + 4);
                float4 b  = *(const float4*)(Ks + kk * 64 + jj0);
                float av[8] = {a0.x, a0.y, a0.z, a0.w, a1.x, a1.y, a1.z, a1.w};
                float bv[4] = {b.x, b.y, b.z, b.w};
#pragma unroll
                for (int ii = 0; ii < 8; ii++)
#pragma unroll
                    for (int jj = 0; jj < 4; jj++)
                        sacc[ii][jj] = fmaf(av[ii], bv[jj], sacc[ii][jj]);
            }
        }

#pragma unroll
        for (int ii = 0; ii < 8; ii++)
#pragma unroll
            for (int jj = 0; jj < 4; jj++) {
                float vv = sacc[ii][jj] * scale;
                if (kv0 + jj0 + jj >= seqlen) vv = -1e30f;
                Ps[(i0 + ii) * PS_STRIDE + jj0 + jj] = vv;
            }

#pragma unroll
        for (int u = 0; u < 8; u++) {
            int slot = tid + 256 * u;
            int j = slot >> 5;
            int dd4 = slot & 31;
            float4 val = ((kv0 + j) < seqlen)
                ? *(const float4*)(v + (size_t)(kv0 + j) * DIM + hoff + dd4 * 4)
                : make_float4(0.f, 0.f, 0.f, 0.f);
            *(float4*)(Vs + j * 128 + dd4 * 4) = val;
        }
        __syncthreads();

        {
            const int i = tid >> 1, sub = tid & 1;
            const int jbase = sub * 32;
            float mold = mrow[i];
            float mloc = -3.0e38f;
#pragma unroll 8
            for (int jj = 0; jj < 32; jj++)
                mloc = fmaxf(mloc, Ps[i * PS_STRIDE + jbase + jj]);
            mloc = fmaxf(mloc, __shfl_xor_sync(0xffffffffu, mloc, 1));
            float mnew = fmaxf(mold, mloc);
            float sum = 0.f;
#pragma unroll 8
            for (int jj = 0; jj < 32; jj++) {
                float p = __expf(Ps[i * PS_STRIDE + jbase + jj] - mnew);
                Ps[i * PS_STRIDE + jbase + jj] = p;
                sum += p;
            }
            sum += __shfl_xor_sync(0xffffffffu, sum, 1);
            if (sub == 0) {
                float al = __expf(mold - mnew);
                arow[i] = al;
                lrow[i] = lrow[i] * al + sum;
                mrow[i] = mnew;
            }
        }
        __syncthreads();

#pragma unroll
        for (int ii = 0; ii < 8; ii++) {
            float al = arow[i0 + ii];
#pragma unroll
            for (int jj = 0; jj < 8; jj++) acc[ii][jj] *= al;
        }
#pragma unroll 4
        for (int kv = 0; kv < 64; kv++) {
            float4 b0 = *(const float4*)(Vs + kv * 128 + d0);
            float4 b1 = *(const float4*)(Vs + kv * 128 + d0 + 4);
            float bv[8] = {b0.x, b0.y, b0.z, b0.w, b1.x, b1.y, b1.z, b1.w};
            float av[8];
#pragma unroll
            for (int ii = 0; ii < 8; ii++)
                av[ii] = Ps[(i0 + ii) * PS_STRIDE + kv];
#pragma unroll
            for (int ii = 0; ii < 8; ii++)
#pragma unroll
                for (int jj = 0; jj < 8; jj++)
                    acc[ii][jj] = fmaf(av[ii], bv[jj], acc[ii][jj]);
        }
    }

#pragma unroll
    for (int ii = 0; ii < 8; ii++) {
        int m = q0 + i0 + ii;
        if (m < S_LEN) {
            float inv = 1.0f / lrow[i0 + ii];
            float* orow = o + (size_t)m * DIM + hoff + d0;
            float4 o0 = make_float4(acc[ii][0] * inv, acc[ii][1] * inv,
                                    acc[ii][2] * inv, acc[ii][3] * inv);
            float4 o1 = make_float4(acc[ii][4] * inv, acc[ii][5] * inv,
                                    acc[ii][6] * inv, acc[ii][7] * inv);
            *(float4*)orow = o0;
            *(float4*)(orow + 4) = o1;
        }
    }
}

// ---------------------------------------------------------------------------
extern "C" void kernel_launch(void* const* d_in, const int* in_sizes, int n_in,
                              void* d_out, int out_size)
{
    const float* x  = (const float*)d_in[0];
    const float* wq = (const float*)d_in[1];
    const float* bq = (const float*)d_in[2];
    const float* wk = (const float*)d_in[3];
    const float* bk = (const float*)d_in[4];
    const float* wv = (const float*)d_in[5];
    const float* bv = (const float*)d_in[6];
    const float* wo = (const float*)d_in[7];
    const float* bo = (const float*)d_in[8];
    const float* gq = (const float*)d_in[9];
    const float* gk = (const float*)d_in[10];
    const int* seq_lens = (const int*)d_in[12];
    float* out = (float*)d_out;

    float *qp, *kp, *vp, *op, *rqp, *rkp;
    cudaGetSymbolAddress((void**)&qp, g_q);
    cudaGetSymbolAddress((void**)&kp, g_k);
    cudaGetSymbolAddress((void**)&vp, g_v);
    cudaGetSymbolAddress((void**)&op, g_o);
    cudaGetSymbolAddress((void**)&rqp, g_rq);
    cudaGetSymbolAddress((void**)&rkp, g_rk);

    dim3 gg(DIM / 128, (S_LEN + 127) / 128);  // 12 x 30
    gemm_nt_bias<<<gg, 256>>>(x, wq, bq, qp, S_LEN, DIM, DIM);
    gemm_nt_bias<<<gg, 256>>>(x, wk, bk, kp, S_LEN, DIM, DIM);
    gemm_nt_bias<<<gg, 256>>>(x, wv, bv, vp, S_LEN, DIM, DIM);

    rms_kernel<<<S_LEN, 256>>>(qp, kp, rqp, rkp);
    rope_kernel<<<S_LEN, 256>>>(qp, kp, gq, gk, rqp, rkp);

    cudaFuncSetAttribute(flash_kernel, cudaFuncAttributeMaxDynamicSharedMemorySize,
                         FLASH_SMEM_BYTES);
    flash_kernel<<<dim3((S_LEN + 127) / 128, NH), 256, FLASH_SMEM_BYTES>>>(
        qp, kp, vp, op, seq_lens);

    gemm_nt_bias<<<gg, 256>>>(op, wo, bo, out, S_LEN, DIM, DIM);
}

// round 6
// speedup vs baseline: 2.6362x; 2.6362x over previous
#include <cuda_runtime.h>
#include <math.h>
#include <stdint.h>

#define S_LEN 3744
#define DIM 1536
#define NH 12
#define HD 128
#define HH 26
#define WW 48
#define EPSN 1e-6f

// scratch (allocation-free rule: __device__ globals)
__device__ float g_q[S_LEN * DIM];
__device__ float g_k[S_LEN * DIM];
__device__ float g_v[S_LEN * DIM];
__device__ float g_o[S_LEN * DIM];
__device__ float g_rq[S_LEN];
__device__ float g_rk[S_LEN];

// ---------------------------------------------------------------------------
// helpers: tf32 convert + m16n8k8 tf32 mma
// ---------------------------------------------------------------------------
__device__ __forceinline__ uint32_t f2tf(float x) {
    uint32_t u;
    asm("cvt.rna.tf32.f32 %0, %1;" : "=r"(u) : "f"(x));
    return u;
}

__device__ __forceinline__ void mma8(
    float& c0, float& c1, float& c2, float& c3,
    uint32_t a0, uint32_t a1, uint32_t a2, uint32_t a3,
    uint32_t b0, uint32_t b1)
{
    asm volatile(
        "mma.sync.aligned.m16n8k8.row.col.f32.tf32.tf32.f32 "
        "{%0,%1,%2,%3}, {%4,%5,%6,%7}, {%8,%9}, {%0,%1,%2,%3};\n"
        : "+f"(c0), "+f"(c1), "+f"(c2), "+f"(c3)
        : "r"(a0), "r"(a1), "r"(a2), "r"(a3), "r"(b0), "r"(b1));
}

// ---------------------------------------------------------------------------
// tf32 GEMM: C[M,N] = A[M,K] @ B[N,K]^T + bias[N]
// 128x128 block, BK=16, 256 threads (8 warps, 2m x 4n of 64x32 warp tiles).
// ---------------------------------------------------------------------------
#define GBK 16
#define GAS 20   // smem stride (16 + 4 pad) -> conflict-free frags

__global__ __launch_bounds__(256, 2) void gemm_nt_tf32(
    const float* __restrict__ A, const float* __restrict__ Bw,
    const float* __restrict__ bias, float* __restrict__ C,
    int M, int N, int K)
{
    __shared__ uint32_t As[128 * GAS];
    __shared__ uint32_t Bs[128 * GAS];

    const int tid = threadIdx.x;
    const int lane = tid & 31;
    const int wid = tid >> 5;
    const int bm = blockIdx.y * 128;
    const int bn = blockIdx.x * 128;
    const int warp_m = (wid >> 2) * 64;
    const int warp_n = (wid & 3) * 32;

    float acc[4][4][4];
#pragma unroll
    for (int a = 0; a < 4; a++)
#pragma unroll
        for (int b = 0; b < 4; b++)
#pragma unroll
            for (int c = 0; c < 4; c++) acc[a][b][c] = 0.f;

    for (int kt = 0; kt < K; kt += GBK) {
        float4 av[2], bv[2];
#pragma unroll
        for (int u = 0; u < 2; u++) {
            int slot = tid + 256 * u;
            int r = slot >> 2;
            int q = (slot & 3) * 4;
            int arow = bm + r;
            av[u] = (arow < M) ? *(const float4*)(A + (size_t)arow * K + kt + q)
                               : make_float4(0.f, 0.f, 0.f, 0.f);
            bv[u] = *(const float4*)(Bw + (size_t)(bn + r) * K + kt + q);
        }
        __syncthreads();
#pragma unroll
        for (int u = 0; u < 2; u++) {
            int slot = tid + 256 * u;
            int r = slot >> 2;
            int q = (slot & 3) * 4;
            As[r * GAS + q + 0] = f2tf(av[u].x);
            As[r * GAS + q + 1] = f2tf(av[u].y);
            As[r * GAS + q + 2] = f2tf(av[u].z);
            As[r * GAS + q + 3] = f2tf(av[u].w);
            Bs[r * GAS + q + 0] = f2tf(bv[u].x);
            Bs[r * GAS + q + 1] = f2tf(bv[u].y);
            Bs[r * GAS + q + 2] = f2tf(bv[u].z);
            Bs[r * GAS + q + 3] = f2tf(bv[u].w);
        }
        __syncthreads();

#pragma unroll
        for (int ks = 0; ks < 2; ks++) {
            const int c = ks * 8 + (lane & 3);
            uint32_t af[4][4];
#pragma unroll
            for (int mt = 0; mt < 4; mt++) {
                int row = warp_m + mt * 16 + (lane >> 2);
                af[mt][0] = As[row * GAS + c];
                af[mt][1] = As[(row + 8) * GAS + c];
                af[mt][2] = As[row * GAS + c + 4];
                af[mt][3] = As[(row + 8) * GAS + c + 4];
            }
            uint32_t bf[4][2];
#pragma unroll
            for (int nt = 0; nt < 4; nt++) {
                int n = warp_n + nt * 8 + (lane >> 2);
                bf[nt][0] = Bs[n * GAS + c];
                bf[nt][1] = Bs[n * GAS + c + 4];
            }
#pragma unroll
            for (int mt = 0; mt < 4; mt++)
#pragma unroll
                for (int nt = 0; nt < 4; nt++)
                    mma8(acc[mt][nt][0], acc[mt][nt][1], acc[mt][nt][2], acc[mt][nt][3],
                         af[mt][0], af[mt][1], af[mt][2], af[mt][3],
                         bf[nt][0], bf[nt][1]);
        }
    }

    // epilogue + bias
#pragma unroll
    for (int mt = 0; mt < 4; mt++) {
        int row0 = bm + warp_m + mt * 16 + (lane >> 2);
#pragma unroll
        for (int nt = 0; nt < 4; nt++) {
            int col = bn + warp_n + nt * 8 + (lane & 3) * 2;
            float b0 = bias[col], b1 = bias[col + 1];
            if (row0 < M) {
                float2 v0 = make_float2(acc[mt][nt][0] + b0, acc[mt][nt][1] + b1);
                *(float2*)(C + (size_t)row0 * N + col) = v0;
            }
            if (row0 + 8 < M) {
                float2 v1 = make_float2(acc[mt][nt][2] + b0, acc[mt][nt][3] + b1);
                *(float2*)(C + (size_t)(row0 + 8) * N + col) = v1;
            }
        }
    }
}

// ---------------------------------------------------------------------------
// Pass 1: per-row inverse RMS of q and k (over full DIM).
// ---------------------------------------------------------------------------
__global__ __launch_bounds__(256) void rms_kernel(
    const float* __restrict__ q, const float* __restrict__ k,
    float* __restrict__ rqv, float* __restrict__ rkv)
{
    const int s = blockIdx.x;
    const int tid = threadIdx.x;
    const float* qr = q + (size_t)s * DIM;
    const float* kr = k + (size_t)s * DIM;

    float sq = 0.f, sk = 0.f;
    for (int i = tid; i < DIM; i += 256) {
        float a = qr[i]; sq = fmaf(a, a, sq);
        float b = kr[i]; sk = fmaf(b, b, sk);
    }
    __shared__ float bq_[256], bk_[256];
    bq_[tid] = sq; bk_[tid] = sk;
    __syncthreads();
    for (int off = 128; off > 0; off >>= 1) {
        if (tid < off) { bq_[tid] += bq_[tid + off]; bk_[tid] += bk_[tid + off]; }
        __syncthreads();
    }
    if (tid == 0) {
        rqv[s] = rsqrtf(bq_[0] * (1.0f / DIM) + EPSN);
        rkv[s] = rsqrtf(bk_[0] * (1.0f / DIM) + EPSN);
    }
}

// ---------------------------------------------------------------------------
// Pass 2: RMSNorm gain + 3D RoPE (angles from first principles, fp64).
// ---------------------------------------------------------------------------
__global__ __launch_bounds__(256) void rope_kernel(
    float* __restrict__ q, float* __restrict__ k,
    const float* __restrict__ gq, const float* __restrict__ gk,
    const float* __restrict__ rqv, const float* __restrict__ rkv)
{
    const int s = blockIdx.x;
    const int tid = threadIdx.x;
    float* qr = q + (size_t)s * DIM;
    float* kr = k + (size_t)s * DIM;
    const float rq = rqv[s];
    const float rk = rkv[s];

    const int f = s / (HH * WW);
    const int rem = s - f * (HH * WW);
    const int hp = rem / WW;
    const int wp = rem - hp * WW;

#pragma unroll
    for (int u = 0; u < 3; u++) {
        int p = tid + u * 256;       // 0..767 = NH*64 pairs
        int h = p >> 6;
        int c = p & 63;
        int pos, j, dim;
        if (c < 22)      { pos = f;  j = c;      dim = 44; }
        else if (c < 43) { pos = hp; j = c - 22; dim = 42; }
        else             { pos = wp; j = c - 43; dim = 42; }
        double inv = pow(10000.0, -2.0 * (double)j / (double)dim);
        double ang = (double)pos * inv;
        double sd, cd;
        sincos(ang, &sd, &cd);
        float cs = (float)cd, sn = (float)sd;

        int base = h * HD + 2 * c;
        float q0 = qr[base] * rq * gq[base];
        float q1 = qr[base + 1] * rq * gq[base + 1];
        qr[base]     = q0 * cs - q1 * sn;
        qr[base + 1] = q0 * sn + q1 * cs;
        float k0 = kr[base] * rk * gk[base];
        float k1 = kr[base + 1] * rk * gk[base + 1];
        kr[base]     = k0 * cs - k1 * sn;
        kr[base + 1] = k0 * sn + k1 * cs;
    }
}

// ---------------------------------------------------------------------------
// Flash attention with tf32 mma. One block per (128 q-rows, head).
// Natural row-major smem tiles; KV chunk = 64.
// ---------------------------------------------------------------------------
#define QKS 132            // stride for Q/K/V tiles (128 + 4)
#define PSS 68             // stride for P tile (64 + 4)
#define FL_SMEM_U32 (128 * QKS + 64 * QKS + 64 * QKS + 128 * PSS + 3 * 128)
#define FL_SMEM_BYTES (FL_SMEM_U32 * 4)

__global__ __launch_bounds__(256, 1) void flash_tf32(
    const float* __restrict__ q, const float* __restrict__ k,
    const float* __restrict__ v, float* __restrict__ o,
    const int* __restrict__ seq_lens)
{
    extern __shared__ uint32_t smu[];
    uint32_t* Qs = smu;                    // [128][QKS] tf32
    uint32_t* Ks = Qs + 128 * QKS;         // [64][QKS]  tf32
    uint32_t* Vs = Ks + 64 * QKS;          // [64][QKS]  tf32
    float* Ps   = (float*)(Vs + 64 * QKS); // [128][PSS] fp32
    float* mrow = Ps + 128 * PSS;
    float* lrow = mrow + 128;
    float* arow = lrow + 128;

    const int tid = threadIdx.x;
    const int lane = tid & 31;
    const int wid = tid >> 5;
    const int head = blockIdx.y;
    const int q0 = blockIdx.x * 128;
    const int seqlen = seq_lens[0];
    const int hoff = head * HD;

    // S-phase warp tiling: 4m x 2n grid of 32x32 tiles
    const int wm_s = (wid >> 1) * 32;
    const int wn_s = (wid & 1) * 32;
    // O-phase warp tiling: 4m x 2n grid of 32x64 tiles
    const int wm_o = (wid >> 1) * 32;
    const int wn_o = (wid & 1) * 64;

    // load Q tile (tf32), natural layout
#pragma unroll
    for (int u = 0; u < 16; u++) {
        int slot = tid + 256 * u;
        int r = slot >> 5;
        int qq = (slot & 31) * 4;
        int grow = q0 + r;
        float4 val = (grow < S_LEN) ? *(const float4*)(q + (size_t)grow * DIM + hoff + qq)
                                    : make_float4(0.f, 0.f, 0.f, 0.f);
        Qs[r * QKS + qq + 0] = f2tf(val.x);
        Qs[r * QKS + qq + 1] = f2tf(val.y);
        Qs[r * QKS + qq + 2] = f2tf(val.z);
        Qs[r * QKS + qq + 3] = f2tf(val.w);
    }
    if (tid < 128) { mrow[tid] = -3.0e38f; lrow[tid] = 0.f; }

    float oacc[2][8][4];
#pragma unroll
    for (int a = 0; a < 2; a++)
#pragma unroll
        for (int b = 0; b < 8; b++)
#pragma unroll
            for (int c = 0; c < 4; c++) oacc[a][b][c] = 0.f;

    const float scale = 0.08838834764831845f;

    for (int kv0 = 0; kv0 < seqlen; kv0 += 64) {
        __syncthreads();   // prev phase-3 done before overwriting K/V
        // load K and V tiles (tf32), natural [kv][d] layout
#pragma unroll
        for (int u = 0; u < 8; u++) {
            int slot = tid + 256 * u;
            int r = slot >> 5;
            int qq = (slot & 31) * 4;
            int grow = kv0 + r;
            float4 kv4, vv4;
            if (grow < seqlen) {
                kv4 = *(const float4*)(k + (size_t)grow * DIM + hoff + qq);
                vv4 = *(const float4*)(v + (size_t)grow * DIM + hoff + qq);
            } else {
                kv4 = make_float4(0.f, 0.f, 0.f, 0.f);
                vv4 = kv4;
            }
            Ks[r * QKS + qq + 0] = f2tf(kv4.x);
            Ks[r * QKS + qq + 1] = f2tf(kv4.y);
            Ks[r * QKS + qq + 2] = f2tf(kv4.z);
            Ks[r * QKS + qq + 3] = f2tf(kv4.w);
            Vs[r * QKS + qq + 0] = f2tf(vv4.x);
            Vs[r * QKS + qq + 1] = f2tf(vv4.y);
            Vs[r * QKS + qq + 2] = f2tf(vv4.z);
            Vs[r * QKS + qq + 3] = f2tf(vv4.w);
        }
        __syncthreads();

        // ---------- S = Q @ K^T : 128x64, per-warp 32x32 ----------
        float sacc[2][4][4];
#pragma unroll
        for (int a = 0; a < 2; a++)
#pragma unroll
            for (int b = 0; b < 4; b++)
#pragma unroll
                for (int c = 0; c < 4; c++) sacc[a][b][c] = 0.f;

#pragma unroll
        for (int ks = 0; ks < 16; ks++) {
            const int c = ks * 8 + (lane & 3);
            uint32_t af[2][4];
#pragma unroll
            for (int mt = 0; mt < 2; mt++) {
                int row = wm_s + mt * 16 + (lane >> 2);
                af[mt][0] = Qs[row * QKS + c];
                af[mt][1] = Qs[(row + 8) * QKS + c];
                af[mt][2] = Qs[row * QKS + c + 4];
                af[mt][3] = Qs[(row + 8) * QKS + c + 4];
            }
            uint32_t bf[4][2];
#pragma unroll
            for (int nt = 0; nt < 4; nt++) {
                int n = wn_s + nt * 8 + (lane >> 2);
                bf[nt][0] = Ks[n * QKS + c];
                bf[nt][1] = Ks[n * QKS + c + 4];
            }
#pragma unroll
            for (int mt = 0; mt < 2; mt++)
#pragma unroll
                for (int nt = 0; nt < 4; nt++)
                    mma8(sacc[mt][nt][0], sacc[mt][nt][1], sacc[mt][nt][2], sacc[mt][nt][3],
                         af[mt][0], af[mt][1], af[mt][2], af[mt][3],
                         bf[nt][0], bf[nt][1]);
        }

        // write scaled+masked scores
#pragma unroll
        for (int mt = 0; mt < 2; mt++) {
            int row = wm_s + mt * 16 + (lane >> 2);
#pragma unroll
            for (int nt = 0; nt < 4; nt++) {
                int col = wn_s + nt * 8 + (lane & 3) * 2;
                bool m0 = (kv0 + col) >= seqlen;
                bool m1 = (kv0 + col + 1) >= seqlen;
                float2 v0 = make_float2(m0 ? -1e30f : sacc[mt][nt][0] * scale,
                                        m1 ? -1e30f : sacc[mt][nt][1] * scale);
                float2 v1 = make_float2(m0 ? -1e30f : sacc[mt][nt][2] * scale,
                                        m1 ? -1e30f : sacc[mt][nt][3] * scale);
                *(float2*)(Ps + row * PSS + col) = v0;
                *(float2*)(Ps + (row + 8) * PSS + col) = v1;
            }
        }
        __syncthreads();

        // ---------- online softmax (verified code, 2 threads/row) ----------
        {
            const int i = tid >> 1, sub = tid & 1;
            const int jbase = sub * 32;
            float mold = mrow[i];
            float mloc = -3.0e38f;
#pragma unroll 8
            for (int jj = 0; jj < 32; jj++)
                mloc = fmaxf(mloc, Ps[i * PSS + jbase + jj]);
            mloc = fmaxf(mloc, __shfl_xor_sync(0xffffffffu, mloc, 1));
            float mnew = fmaxf(mold, mloc);
            float sum = 0.f;
#pragma unroll 8
            for (int jj = 0; jj < 32; jj++) {
                float p = __expf(Ps[i * PSS + jbase + jj] - mnew);
                Ps[i * PSS + jbase + jj] = p;
                sum += p;
            }
            sum += __shfl_xor_sync(0xffffffffu, sum, 1);
            if (sub == 0) {
                float al = __expf(mold - mnew);
                arow[i] = al;
                lrow[i] = lrow[i] * al + sum;
                mrow[i] = mnew;
            }
        }
        __syncthreads();

        // ---------- O = alpha*O + P @ V : per-warp 32x64 ----------
#pragma unroll
        for (int mt = 0; mt < 2; mt++) {
            int row = wm_o + mt * 16 + (lane >> 2);
            float al0 = arow[row];
            float al1 = arow[row + 8];
#pragma unroll
            for (int nt = 0; nt < 8; nt++) {
                oacc[mt][nt][0] *= al0;
                oacc[mt][nt][1] *= al0;
                oacc[mt][nt][2] *= al1;
                oacc[mt][nt][3] *= al1;
            }
        }
#pragma unroll
        for (int ks = 0; ks < 8; ks++) {
            const int c = ks * 8 + (lane & 3);
            uint32_t paf[2][4];
#pragma unroll
            for (int mt = 0; mt < 2; mt++) {
                int row = wm_o + mt * 16 + (lane >> 2);
                paf[mt][0] = __float_as_uint(Ps[row * PSS + c]);
                paf[mt][1] = __float_as_uint(Ps[(row + 8) * PSS + c]);
                paf[mt][2] = __float_as_uint(Ps[row * PSS + c + 4]);
                paf[mt][3] = __float_as_uint(Ps[(row + 8) * PSS + c + 4]);
            }
#pragma unroll
            for (int nt = 0; nt < 8; nt++) {
                int n = wn_o + nt * 8 + (lane >> 2);
                uint32_t b0 = Vs[c * QKS + n];
                uint32_t b1 = Vs[(c + 4) * QKS + n];
#pragma unroll
                for (int mt = 0; mt < 2; mt++)
                    mma8(oacc[mt][nt][0], oacc[mt][nt][1], oacc[mt][nt][2], oacc[mt][nt][3],
                         paf[mt][0], paf[mt][1], paf[mt][2], paf[mt][3], b0, b1);
            }
        }
    }

    // epilogue: divide by l, store
#pragma unroll
    for (int mt = 0; mt < 2; mt++) {
        int lrow0 = wm_o + mt * 16 + (lane >> 2);
        int grow0 = q0 + lrow0;
        float inv0 = 1.0f / lrow[lrow0];
        float inv1 = 1.0f / lrow[lrow0 + 8];
#pragma unroll
        for (int nt = 0; nt < 8; nt++) {
            int col = hoff + wn_o + nt * 8 + (lane & 3) * 2;
            if (grow0 < S_LEN) {
                float2 v0 = make_float2(oacc[mt][nt][0] * inv0, oacc[mt][nt][1] * inv0);
                *(float2*)(o + (size_t)grow0 * DIM + col) = v0;
            }
            if (grow0 + 8 < S_LEN) {
                float2 v1 = make_float2(oacc[mt][nt][2] * inv1, oacc[mt][nt][3] * inv1);
                *(float2*)(o + (size_t)(grow0 + 8) * DIM + col) = v1;
            }
        }
    }
}

// ---------------------------------------------------------------------------
extern "C" void kernel_launch(void* const* d_in, const int* in_sizes, int n_in,
                              void* d_out, int out_size)
{
    const float* x  = (const float*)d_in[0];
    const float* wq = (const float*)d_in[1];
    const float* bq = (const float*)d_in[2];
    const float* wk = (const float*)d_in[3];
    const float* bk = (const float*)d_in[4];
    const float* wv = (const float*)d_in[5];
    const float* bv = (const float*)d_in[6];
    const float* wo = (const float*)d_in[7];
    const float* bo = (const float*)d_in[8];
    const float* gq = (const float*)d_in[9];
    const float* gk = (const float*)d_in[10];
    const int* seq_lens = (const int*)d_in[12];
    float* out = (float*)d_out;

    float *qp, *kp, *vp, *op, *rqp, *rkp;
    cudaGetSymbolAddress((void**)&qp, g_q);
    cudaGetSymbolAddress((void**)&kp, g_k);
    cudaGetSymbolAddress((void**)&vp, g_v);
    cudaGetSymbolAddress((void**)&op, g_o);
    cudaGetSymbolAddress((void**)&rqp, g_rq);
    cudaGetSymbolAddress((void**)&rkp, g_rk);

    dim3 gg(DIM / 128, (S_LEN + 127) / 128);  // 12 x 30
    gemm_nt_tf32<<<gg, 256>>>(x, wq, bq, qp, S_LEN, DIM, DIM);
    gemm_nt_tf32<<<gg, 256>>>(x, wk, bk, kp, S_LEN, DIM, DIM);
    gemm_nt_tf32<<<gg, 256>>>(x, wv, bv, vp, S_LEN, DIM, DIM);

    rms_kernel<<<S_LEN, 256>>>(qp, kp, rqp, rkp);
    rope_kernel<<<S_LEN, 256>>>(qp, kp, gq, gk, rqp, rkp);

    cudaFuncSetAttribute(flash_tf32, cudaFuncAttributeMaxDynamicSharedMemorySize,
                         FL_SMEM_BYTES);
    flash_tf32<<<dim3((S_LEN + 127) / 128, NH), 256, FL_SMEM_BYTES>>>(
        qp, kp, vp, op, seq_lens);

    gemm_nt_tf32<<<gg, 256>>>(op, wo, bo, out, S_LEN, DIM, DIM);
}

// round 7
// speedup vs baseline: 4.7115x; 1.7872x over previous
#include <cuda_runtime.h>
#include <math.h>
#include <stdint.h>

#define S_LEN 3744
#define DIM 1536
#define NH 12
#define HD 128
#define HH 26
#define WW 48
#define EPSN 1e-6f

// scratch (allocation-free rule: __device__ globals)
__device__ float g_q[S_LEN * DIM];
__device__ float g_k[S_LEN * DIM];
__device__ float g_v[S_LEN * DIM];
__device__ float g_o[S_LEN * DIM];

// ---------------------------------------------------------------------------
// helpers: tf32 convert + m16n8k8 tf32 mma
// ---------------------------------------------------------------------------
__device__ __forceinline__ uint32_t f2tf(float x) {
    uint32_t u;
    asm("cvt.rna.tf32.f32 %0, %1;" : "=r"(u) : "f"(x));
    return u;
}

__device__ __forceinline__ void mma8(
    float& c0, float& c1, float& c2, float& c3,
    uint32_t a0, uint32_t a1, uint32_t a2, uint32_t a3,
    uint32_t b0, uint32_t b1)
{
    asm volatile(
        "mma.sync.aligned.m16n8k8.row.col.f32.tf32.tf32.f32 "
        "{%0,%1,%2,%3}, {%4,%5,%6,%7}, {%8,%9}, {%0,%1,%2,%3};\n"
        : "+f"(c0), "+f"(c1), "+f"(c2), "+f"(c3)
        : "r"(a0), "r"(a1), "r"(a2), "r"(a3), "r"(b0), "r"(b1));
}

// ---------------------------------------------------------------------------
// tf32 GEMM: C_z[M,N] = A[M,K] @ W_z[N,K]^T + bias_z[N], z = blockIdx.z
// 128x128 block, BK=16, 256 threads, register-prefetched k-slabs.
// ---------------------------------------------------------------------------
#define GBK 16
#define GAS 20   // smem stride (16 + 4 pad)

__global__ __launch_bounds__(256, 2) void gemm_nt_tf32(
    const float* __restrict__ A,
    const float* __restrict__ w0, const float* __restrict__ w1, const float* __restrict__ w2,
    const float* __restrict__ b0p, const float* __restrict__ b1p, const float* __restrict__ b2p,
    float* __restrict__ c0p, float* __restrict__ c1p, float* __restrict__ c2p,
    int M, int N, int K)
{
    __shared__ uint32_t As[128 * GAS];
    __shared__ uint32_t Bs[128 * GAS];

    const int z = blockIdx.z;
    const float* Bw   = (z == 0) ? w0 : (z == 1) ? w1 : w2;
    const float* bias = (z == 0) ? b0p : (z == 1) ? b1p : b2p;
    float* C          = (z == 0) ? c0p : (z == 1) ? c1p : c2p;

    const int tid = threadIdx.x;
    const int lane = tid & 31;
    const int wid = tid >> 5;
    const int bm = blockIdx.y * 128;
    const int bn = blockIdx.x * 128;
    const int warp_m = (wid >> 2) * 64;
    const int warp_n = (wid & 3) * 32;

    float acc[4][4][4];
#pragma unroll
    for (int a = 0; a < 4; a++)
#pragma unroll
        for (int b = 0; b < 4; b++)
#pragma unroll
            for (int c = 0; c < 4; c++) acc[a][b][c] = 0.f;

    const int r_ld = tid >> 2;            // 0..63 per 256-slot group -> slot>>2
    const int q_ld = (tid & 3) * 4;
    (void)r_ld; (void)q_ld;

    float4 av[2], bv[2];
#pragma unroll
    for (int u = 0; u < 2; u++) {
        int slot = tid + 256 * u;
        int r = slot >> 2;
        int q = (slot & 3) * 4;
        int arow = bm + r;
        av[u] = (arow < M) ? *(const float4*)(A + (size_t)arow * K + q)
                           : make_float4(0.f, 0.f, 0.f, 0.f);
        bv[u] = *(const float4*)(Bw + (size_t)(bn + r) * K + q);
    }

    for (int kt = 0; kt < K; kt += GBK) {
        __syncthreads();
#pragma unroll
        for (int u = 0; u < 2; u++) {
            int slot = tid + 256 * u;
            int r = slot >> 2;
            int q = (slot & 3) * 4;
            As[r * GAS + q + 0] = f2tf(av[u].x);
            As[r * GAS + q + 1] = f2tf(av[u].y);
            As[r * GAS + q + 2] = f2tf(av[u].z);
            As[r * GAS + q + 3] = f2tf(av[u].w);
            Bs[r * GAS + q + 0] = f2tf(bv[u].x);
            Bs[r * GAS + q + 1] = f2tf(bv[u].y);
            Bs[r * GAS + q + 2] = f2tf(bv[u].z);
            Bs[r * GAS + q + 3] = f2tf(bv[u].w);
        }
        __syncthreads();

        // prefetch next k-slab (overlaps mma below)
        if (kt + GBK < K) {
#pragma unroll
            for (int u = 0; u < 2; u++) {
                int slot = tid + 256 * u;
                int r = slot >> 2;
                int q = (slot & 3) * 4;
                int arow = bm + r;
                av[u] = (arow < M) ? *(const float4*)(A + (size_t)arow * K + kt + GBK + q)
                                   : make_float4(0.f, 0.f, 0.f, 0.f);
                bv[u] = *(const float4*)(Bw + (size_t)(bn + r) * K + kt + GBK + q);
            }
        }

#pragma unroll
        for (int ks = 0; ks < 2; ks++) {
            const int c = ks * 8 + (lane & 3);
            uint32_t af[4][4];
#pragma unroll
            for (int mt = 0; mt < 4; mt++) {
                int row = warp_m + mt * 16 + (lane >> 2);
                af[mt][0] = As[row * GAS + c];
                af[mt][1] = As[(row + 8) * GAS + c];
                af[mt][2] = As[row * GAS + c + 4];
                af[mt][3] = As[(row + 8) * GAS + c + 4];
            }
            uint32_t bf[4][2];
#pragma unroll
            for (int nt = 0; nt < 4; nt++) {
                int n = warp_n + nt * 8 + (lane >> 2);
                bf[nt][0] = Bs[n * GAS + c];
                bf[nt][1] = Bs[n * GAS + c + 4];
            }
#pragma unroll
            for (int mt = 0; mt < 4; mt++)
#pragma unroll
                for (int nt = 0; nt < 4; nt++)
                    mma8(acc[mt][nt][0], acc[mt][nt][1], acc[mt][nt][2], acc[mt][nt][3],
                         af[mt][0], af[mt][1], af[mt][2], af[mt][3],
                         bf[nt][0], bf[nt][1]);
        }
    }

#pragma unroll
    for (int mt = 0; mt < 4; mt++) {
        int row0 = bm + warp_m + mt * 16 + (lane >> 2);
#pragma unroll
        for (int nt = 0; nt < 4; nt++) {
            int col = bn + warp_n + nt * 8 + (lane & 3) * 2;
            float bb0 = bias[col], bb1 = bias[col + 1];
            if (row0 < M) {
                float2 v0 = make_float2(acc[mt][nt][0] + bb0, acc[mt][nt][1] + bb1);
                *(float2*)(C + (size_t)row0 * N + col) = v0;
            }
            if (row0 + 8 < M) {
                float2 v1 = make_float2(acc[mt][nt][2] + bb0, acc[mt][nt][3] + bb1);
                *(float2*)(C + (size_t)(row0 + 8) * N + col) = v1;
            }
        }
    }
}

// ---------------------------------------------------------------------------
// Fused RMSNorm + 3D RoPE (angles from first principles, fp64), in place.
// ---------------------------------------------------------------------------
__global__ __launch_bounds__(256) void rmsrope_kernel(
    float* __restrict__ q, float* __restrict__ k,
    const float* __restrict__ gq, const float* __restrict__ gk)
{
    const int s = blockIdx.x;
    const int tid = threadIdx.x;
    float* qr = q + (size_t)s * DIM;
    float* kr = k + (size_t)s * DIM;

    float sq = 0.f, sk = 0.f;
    for (int i = tid; i < DIM; i += 256) {
        float a = qr[i]; sq = fmaf(a, a, sq);
        float b = kr[i]; sk = fmaf(b, b, sk);
    }
    __shared__ float bq_[256], bk_[256];
    bq_[tid] = sq; bk_[tid] = sk;
    __syncthreads();
    for (int off = 128; off > 0; off >>= 1) {
        if (tid < off) { bq_[tid] += bq_[tid + off]; bk_[tid] += bk_[tid + off]; }
        __syncthreads();
    }
    const float rq = rsqrtf(bq_[0] * (1.0f / DIM) + EPSN);
    const float rk = rsqrtf(bk_[0] * (1.0f / DIM) + EPSN);

    const int f = s / (HH * WW);
    const int rem = s - f * (HH * WW);
    const int hp = rem / WW;
    const int wp = rem - hp * WW;

#pragma unroll
    for (int u = 0; u < 3; u++) {
        int p = tid + u * 256;       // 0..767 = NH*64 pairs
        int h = p >> 6;
        int c = p & 63;
        int pos, j, dim;
        if (c < 22)      { pos = f;  j = c;      dim = 44; }
        else if (c < 43) { pos = hp; j = c - 22; dim = 42; }
        else             { pos = wp; j = c - 43; dim = 42; }
        double inv = pow(10000.0, -2.0 * (double)j / (double)dim);
        double ang = (double)pos * inv;
        double sd, cd;
        sincos(ang, &sd, &cd);
        float cs = (float)cd, sn = (float)sd;

        int base = h * HD + 2 * c;
        float q0 = qr[base] * rq * gq[base];
        float q1 = qr[base + 1] * rq * gq[base + 1];
        qr[base]     = q0 * cs - q1 * sn;
        qr[base + 1] = q0 * sn + q1 * cs;
        float k0 = kr[base] * rk * gk[base];
        float k1 = kr[base + 1] * rk * gk[base + 1];
        kr[base]     = k0 * cs - k1 * sn;
        kr[base + 1] = k0 * sn + k1 * cs;
    }
}

// ---------------------------------------------------------------------------
// Flash attention, tf32 mma. One block per (64 q-rows, head). 256 threads.
// KV chunk = 64, register-prefetched.
// ---------------------------------------------------------------------------
#define QT 64
#define QKS 132            // stride for Q/K/V tiles (128 + 4)
#define PSS 68             // stride for P tile (64 + 4)
#define FL_SMEM_U32 (3 * QT * QKS + QT * PSS + 3 * QT)
#define FL_SMEM_BYTES (FL_SMEM_U32 * 4)

__global__ __launch_bounds__(256, 1) void flash_tf32(
    const float* __restrict__ q, const float* __restrict__ k,
    const float* __restrict__ v, float* __restrict__ o,
    const int* __restrict__ seq_lens)
{
    extern __shared__ uint32_t smu[];
    uint32_t* Qs = smu;                    // [64][QKS] tf32
    uint32_t* Ks = Qs + QT * QKS;          // [64][QKS] tf32
    uint32_t* Vs = Ks + QT * QKS;          // [64][QKS] tf32
    float* Ps   = (float*)(Vs + QT * QKS); // [64][PSS] fp32
    float* mrow = Ps + QT * PSS;
    float* lrow = mrow + QT;
    float* arow = lrow + QT;

    const int tid = threadIdx.x;
    const int lane = tid & 31;
    const int wid = tid >> 5;
    const int head = blockIdx.y;
    const int q0 = blockIdx.x * QT;
    const int seqlen = seq_lens[0];
    const int hoff = head * HD;

    // S-phase: 64x64, warp grid 2m x 4n, warp tile 32x16
    const int wm_s = (wid >> 2) * 32;
    const int wn_s = (wid & 3) * 16;
    // O-phase: 64x128, warp grid 2m x 4n, warp tile 32x32
    const int wm_o = (wid >> 2) * 32;
    const int wn_o = (wid & 3) * 32;

    // load Q tile (tf32)
#pragma unroll
    for (int u = 0; u < 8; u++) {
        int slot = tid + 256 * u;
        int r = slot >> 5;
        int qq = (slot & 31) * 4;
        int grow = q0 + r;
        float4 val = (grow < S_LEN) ? *(const float4*)(q + (size_t)grow * DIM + hoff + qq)
                                    : make_float4(0.f, 0.f, 0.f, 0.f);
        Qs[r * QKS + qq + 0] = f2tf(val.x);
        Qs[r * QKS + qq + 1] = f2tf(val.y);
        Qs[r * QKS + qq + 2] = f2tf(val.z);
        Qs[r * QKS + qq + 3] = f2tf(val.w);
    }
    if (tid < QT) { mrow[tid] = -3.0e38f; lrow[tid] = 0.f; }

    float oacc[2][4][4];
#pragma unroll
    for (int a = 0; a < 2; a++)
#pragma unroll
        for (int b = 0; b < 4; b++)
#pragma unroll
            for (int c = 0; c < 4; c++) oacc[a][b][c] = 0.f;

    const float scale = 0.08838834764831845f;

    // prefetch chunk 0
    float4 kreg[8], vreg[8];
#pragma unroll
    for (int u = 0; u < 8; u++) {
        int slot = tid + 256 * u;
        int r = slot >> 5;
        int qq = (slot & 31) * 4;
        if (r < seqlen) {
            kreg[u] = *(const float4*)(k + (size_t)r * DIM + hoff + qq);
            vreg[u] = *(const float4*)(v + (size_t)r * DIM + hoff + qq);
        } else {
            kreg[u] = make_float4(0.f, 0.f, 0.f, 0.f);
            vreg[u] = kreg[u];
        }
    }

    for (int kv0 = 0; kv0 < seqlen; kv0 += 64) {
        __syncthreads();   // prev O-phase done before overwriting K/V
#pragma unroll
        for (int u = 0; u < 8; u++) {
            int slot = tid + 256 * u;
            int r = slot >> 5;
            int qq = (slot & 31) * 4;
            Ks[r * QKS + qq + 0] = f2tf(kreg[u].x);
            Ks[r * QKS + qq + 1] = f2tf(kreg[u].y);
            Ks[r * QKS + qq + 2] = f2tf(kreg[u].z);
            Ks[r * QKS + qq + 3] = f2tf(kreg[u].w);
            Vs[r * QKS + qq + 0] = f2tf(vreg[u].x);
            Vs[r * QKS + qq + 1] = f2tf(vreg[u].y);
            Vs[r * QKS + qq + 2] = f2tf(vreg[u].z);
            Vs[r * QKS + qq + 3] = f2tf(vreg[u].w);
        }
        __syncthreads();

        // prefetch next chunk (overlaps all mma + softmax below)
        if (kv0 + 64 < seqlen) {
#pragma unroll
            for (int u = 0; u < 8; u++) {
                int slot = tid + 256 * u;
                int r = kv0 + 64 + (slot >> 5);
                int qq = (slot & 31) * 4;
                if (r < seqlen) {
                    kreg[u] = *(const float4*)(k + (size_t)r * DIM + hoff + qq);
                    vreg[u] = *(const float4*)(v + (size_t)r * DIM + hoff + qq);
                } else {
                    kreg[u] = make_float4(0.f, 0.f, 0.f, 0.f);
                    vreg[u] = kreg[u];
                }
            }
        }

        // ---------- S = Q @ K^T : 64x64, per-warp 32x16 ----------
        float sacc[2][2][4];
#pragma unroll
        for (int a = 0; a < 2; a++)
#pragma unroll
            for (int b = 0; b < 2; b++)
#pragma unroll
                for (int c = 0; c < 4; c++) sacc[a][b][c] = 0.f;

#pragma unroll
        for (int ks = 0; ks < 16; ks++) {
            const int c = ks * 8 + (lane & 3);
            uint32_t af[2][4];
#pragma unroll
            for (int mt = 0; mt < 2; mt++) {
                int row = wm_s + mt * 16 + (lane >> 2);
                af[mt][0] = Qs[row * QKS + c];
                af[mt][1] = Qs[(row + 8) * QKS + c];
                af[mt][2] = Qs[row * QKS + c + 4];
                af[mt][3] = Qs[(row + 8) * QKS + c + 4];
            }
            uint32_t bf[2][2];
#pragma unroll
            for (int nt = 0; nt < 2; nt++) {
                int n = wn_s + nt * 8 + (lane >> 2);
                bf[nt][0] = Ks[n * QKS + c];
                bf[nt][1] = Ks[n * QKS + c + 4];
            }
#pragma unroll
            for (int mt = 0; mt < 2; mt++)
#pragma unroll
                for (int nt = 0; nt < 2; nt++)
                    mma8(sacc[mt][nt][0], sacc[mt][nt][1], sacc[mt][nt][2], sacc[mt][nt][3],
                         af[mt][0], af[mt][1], af[mt][2], af[mt][3],
                         bf[nt][0], bf[nt][1]);
        }

        // write scaled+masked scores
#pragma unroll
        for (int mt = 0; mt < 2; mt++) {
            int row = wm_s + mt * 16 + (lane >> 2);
#pragma unroll
            for (int nt = 0; nt < 2; nt++) {
                int col = wn_s + nt * 8 + (lane & 3) * 2;
                bool m0 = (kv0 + col) >= seqlen;
                bool m1 = (kv0 + col + 1) >= seqlen;
                float2 v0 = make_float2(m0 ? -1e30f : sacc[mt][nt][0] * scale,
                                        m1 ? -1e30f : sacc[mt][nt][1] * scale);
                float2 v1 = make_float2(m0 ? -1e30f : sacc[mt][nt][2] * scale,
                                        m1 ? -1e30f : sacc[mt][nt][3] * scale);
                *(float2*)(Ps + row * PSS + col) = v0;
                *(float2*)(Ps + (row + 8) * PSS + col) = v1;
            }
        }
        __syncthreads();

        // ---------- online softmax (4 threads per row) ----------
        {
            const int i = tid >> 2, sub = tid & 3;
            const int jbase = sub * 16;
            float mold = mrow[i];
            float mloc = -3.0e38f;
#pragma unroll
            for (int jj = 0; jj < 16; jj++)
                mloc = fmaxf(mloc, Ps[i * PSS + jbase + jj]);
            mloc = fmaxf(mloc, __shfl_xor_sync(0xffffffffu, mloc, 1));
            mloc = fmaxf(mloc, __shfl_xor_sync(0xffffffffu, mloc, 2));
            float mnew = fmaxf(mold, mloc);
            float sum = 0.f;
#pragma unroll
            for (int jj = 0; jj < 16; jj++) {
                float p = __expf(Ps[i * PSS + jbase + jj] - mnew);
                Ps[i * PSS + jbase + jj] = p;
                sum += p;
            }
            sum += __shfl_xor_sync(0xffffffffu, sum, 1);
            sum += __shfl_xor_sync(0xffffffffu, sum, 2);
            if (sub == 0) {
                float al = __expf(mold - mnew);
                arow[i] = al;
                lrow[i] = lrow[i] * al + sum;
                mrow[i] = mnew;
            }
        }
        __syncthreads();

        // ---------- O = alpha*O + P @ V : per-warp 32x32 ----------
#pragma unroll
        for (int mt = 0; mt < 2; mt++) {
            int row = wm_o + mt * 16 + (lane >> 2);
            float al0 = arow[row];
            float al1 = arow[row + 8];
#pragma unroll
            for (int nt = 0; nt < 4; nt++) {
                oacc[mt][nt][0] *= al0;
                oacc[mt][nt][1] *= al0;
                oacc[mt][nt][2] *= al1;
                oacc[mt][nt][3] *= al1;
            }
        }
#pragma unroll
        for (int ks = 0; ks < 8; ks++) {
            const int c = ks * 8 + (lane & 3);
            uint32_t paf[2][4];
#pragma unroll
            for (int mt = 0; mt < 2; mt++) {
                int row = wm_o + mt * 16 + (lane >> 2);
                paf[mt][0] = __float_as_uint(Ps[row * PSS + c]);
                paf[mt][1] = __float_as_uint(Ps[(row + 8) * PSS + c]);
                paf[mt][2] = __float_as_uint(Ps[row * PSS + c + 4]);
                paf[mt][3] = __float_as_uint(Ps[(row + 8) * PSS + c + 4]);
            }
#pragma unroll
            for (int nt = 0; nt < 4; nt++) {
                int n = wn_o + nt * 8 + (lane >> 2);
                uint32_t b0 = Vs[c * QKS + n];
                uint32_t b1 = Vs[(c + 4) * QKS + n];
#pragma unroll
                for (int mt = 0; mt < 2; mt++)
                    mma8(oacc[mt][nt][0], oacc[mt][nt][1], oacc[mt][nt][2], oacc[mt][nt][3],
                         paf[mt][0], paf[mt][1], paf[mt][2], paf[mt][3], b0, b1);
            }
        }
    }

    // epilogue: divide by l, store
#pragma unroll
    for (int mt = 0; mt < 2; mt++) {
        int lrow0 = wm_o + mt * 16 + (lane >> 2);
        int grow0 = q0 + lrow0;
        float inv0 = 1.0f / lrow[lrow0];
        float inv1 = 1.0f / lrow[lrow0 + 8];
#pragma unroll
        for (int nt = 0; nt < 4; nt++) {
            int col = hoff + wn_o + nt * 8 + (lane & 3) * 2;
            if (grow0 < S_LEN) {
                float2 v0 = make_float2(oacc[mt][nt][0] * inv0, oacc[mt][nt][1] * inv0);
                *(float2*)(o + (size_t)grow0 * DIM + col) = v0;
            }
            if (grow0 + 8 < S_LEN) {
                float2 v1 = make_float2(oacc[mt][nt][2] * inv1, oacc[mt][nt][3] * inv1);
                *(float2*)(o + (size_t)(grow0 + 8) * DIM + col) = v1;
            }
        }
    }
}

// ---------------------------------------------------------------------------
extern "C" void kernel_launch(void* const* d_in, const int* in_sizes, int n_in,
                              void* d_out, int out_size)
{
    const float* x  = (const float*)d_in[0];
    const float* wq = (const float*)d_in[1];
    const float* bq = (const float*)d_in[2];
    const float* wk = (const float*)d_in[3];
    const float* bk = (const float*)d_in[4];
    const float* wv = (const float*)d_in[5];
    const float* bv = (const float*)d_in[6];
    const float* wo = (const float*)d_in[7];
    const float* bo = (const float*)d_in[8];
    const float* gq = (const float*)d_in[9];
    const float* gk = (const float*)d_in[10];
    const int* seq_lens = (const int*)d_in[12];
    float* out = (float*)d_out;

    float *qp, *kp, *vp, *op;
    cudaGetSymbolAddress((void**)&qp, g_q);
    cudaGetSymbolAddress((void**)&kp, g_k);
    cudaGetSymbolAddress((void**)&vp, g_v);
    cudaGetSymbolAddress((void**)&op, g_o);

    // fused Q/K/V projections (z selects weight/bias/output)
    dim3 gqkv(DIM / 128, (S_LEN + 127) / 128, 3);
    gemm_nt_tf32<<<gqkv, 256>>>(x, wq, wk, wv, bq, bk, bv, qp, kp, vp,
                                S_LEN, DIM, DIM);

    rmsrope_kernel<<<S_LEN, 256>>>(qp, kp, gq, gk);

    cudaFuncSetAttribute(flash_tf32, cudaFuncAttributeMaxDynamicSharedMemorySize,
                         FL_SMEM_BYTES);
    flash_tf32<<<dim3((S_LEN + QT - 1) / QT, NH), 256, FL_SMEM_BYTES>>>(
        qp, kp, vp, op, seq_lens);

    // output projection
    dim3 go(DIM / 128, (S_LEN + 127) / 128, 1);
    gemm_nt_tf32<<<go, 256>>>(op, wo, wo, wo, bo, bo, bo, out, out, out,
                              S_LEN, DIM, DIM);
}

// round 8
// speedup vs baseline: 5.0058x; 1.0625x over previous
#include <cuda_runtime.h>
#include <math.h>
#include <stdint.h>

#define S_LEN 3744
#define DIM 1536
#define NH 12
#define HD 128
#define HH 26
#define WW 48
#define EPSN 1e-6f

// scratch (allocation-free rule: __device__ globals)
__device__ float g_q[S_LEN * DIM];
__device__ float g_k[S_LEN * DIM];
__device__ float g_v[S_LEN * DIM];
__device__ float g_o[S_LEN * DIM];
__device__ float g_x[S_LEN * DIM];        // tf32-rounded x
__device__ float g_wq[DIM * DIM];         // tf32-rounded weights
__device__ float g_wk[DIM * DIM];
__device__ float g_wv[DIM * DIM];
__device__ float g_wo[DIM * DIM];

// ---------------------------------------------------------------------------
// helpers
// ---------------------------------------------------------------------------
__device__ __forceinline__ uint32_t f2tf(float x) {
    uint32_t u;
    asm("cvt.rna.tf32.f32 %0, %1;" : "=r"(u) : "f"(x));
    return u;
}

__device__ __forceinline__ void mma8(
    float& c0, float& c1, float& c2, float& c3,
    uint32_t a0, uint32_t a1, uint32_t a2, uint32_t a3,
    uint32_t b0, uint32_t b1)
{
    asm volatile(
        "mma.sync.aligned.m16n8k8.row.col.f32.tf32.tf32.f32 "
        "{%0,%1,%2,%3}, {%4,%5,%6,%7}, {%8,%9}, {%0,%1,%2,%3};\n"
        : "+f"(c0), "+f"(c1), "+f"(c2), "+f"(c3)
        : "r"(a0), "r"(a1), "r"(a2), "r"(a3), "r"(b0), "r"(b1));
}

__device__ __forceinline__ void cp16(uint32_t dst_smem, const void* src, int srcsz) {
    asm volatile("cp.async.ca.shared.global [%0], [%1], 16, %2;\n"
                 :: "r"(dst_smem), "l"(src), "r"(srcsz));
}
#define CP_COMMIT() asm volatile("cp.async.commit_group;\n")
#define CP_WAIT0()  asm volatile("cp.async.wait_group 0;\n")

// ---------------------------------------------------------------------------
// pre-round: out[i] = tf32_rna(in[i]), vectorized by 4
// ---------------------------------------------------------------------------
__global__ __launch_bounds__(256) void pre_round(
    const float* __restrict__ in, float* __restrict__ out, int n4)
{
    int i = blockIdx.x * 256 + threadIdx.x;
    if (i < n4) {
        float4 v = ((const float4*)in)[i];
        float4 r;
        r.x = __uint_as_float(f2tf(v.x));
        r.y = __uint_as_float(f2tf(v.y));
        r.z = __uint_as_float(f2tf(v.z));
        r.w = __uint_as_float(f2tf(v.w));
        ((float4*)out)[i] = r;
    }
}

// ---------------------------------------------------------------------------
// tf32 GEMM with cp.async 2-stage pipeline. Operands pre-rounded tf32 bits.
// C_z[M,N] = A[M,K] @ W_z[N,K]^T + bias_z[N]; optional tf32 rounding of C.
// ---------------------------------------------------------------------------
#define GBK 16
#define GAS 20

__global__ __launch_bounds__(256, 2) void gemm_nt_tf32(
    const float* __restrict__ A,
    const float* __restrict__ w0, const float* __restrict__ w1, const float* __restrict__ w2,
    const float* __restrict__ b0p, const float* __restrict__ b1p, const float* __restrict__ b2p,
    float* __restrict__ c0p, float* __restrict__ c1p, float* __restrict__ c2p,
    int M, int N, int K, int round_out)
{
    __shared__ uint32_t As[2][128 * GAS];
    __shared__ uint32_t Bs[2][128 * GAS];

    const int z = blockIdx.z;
    const float* Bw   = (z == 0) ? w0 : (z == 1) ? w1 : w2;
    const float* bias = (z == 0) ? b0p : (z == 1) ? b1p : b2p;
    float* C          = (z == 0) ? c0p : (z == 1) ? c1p : c2p;

    const int tid = threadIdx.x;
    const int lane = tid & 31;
    const int wid = tid >> 5;
    const int bm = blockIdx.y * 128;
    const int bn = blockIdx.x * 128;
    const int warp_m = (wid >> 2) * 64;
    const int warp_n = (wid & 3) * 32;

    float acc[4][4][4];
#pragma unroll
    for (int a = 0; a < 4; a++)
#pragma unroll
        for (int b = 0; b < 4; b++)
#pragma unroll
            for (int c = 0; c < 4; c++) acc[a][b][c] = 0.f;

    // cp.async load mapping: slot -> row r (0..127), k-quad q
    const int r0s = tid >> 2;
    const int q0s = (tid & 3) * 4;
    const int r1s = (tid + 256) >> 2;
    const int q1s = q0s;  // (slot+256)&3 == slot&3

    auto issue = [&](int st, int kt) {
        int a0sz = (bm + r0s) < M ? 16 : 0;
        int a1sz = (bm + r1s) < M ? 16 : 0;
        cp16((uint32_t)__cvta_generic_to_shared(&As[st][r0s * GAS + q0s]),
             A + (size_t)(bm + r0s) * K + kt + q0s, a0sz);
        cp16((uint32_t)__cvta_generic_to_shared(&As[st][r1s * GAS + q1s]),
             A + (size_t)(bm + r1s) * K + kt + q1s, a1sz);
        cp16((uint32_t)__cvta_generic_to_shared(&Bs[st][r0s * GAS + q0s]),
             Bw + (size_t)(bn + r0s) * K + kt + q0s, 16);
        cp16((uint32_t)__cvta_generic_to_shared(&Bs[st][r1s * GAS + q1s]),
             Bw + (size_t)(bn + r1s) * K + kt + q1s, 16);
    };

    issue(0, 0);
    CP_COMMIT();

    int st = 0;
    for (int kt = 0; kt < K; kt += GBK, st ^= 1) {
        CP_WAIT0();
        __syncthreads();
        if (kt + GBK < K) {
            issue(st ^ 1, kt + GBK);
            CP_COMMIT();
        }

#pragma unroll
        for (int ks = 0; ks < 2; ks++) {
            const int c = ks * 8 + (lane & 3);
            uint32_t af[4][4];
#pragma unroll
            for (int mt = 0; mt < 4; mt++) {
                int row = warp_m + mt * 16 + (lane >> 2);
                af[mt][0] = As[st][row * GAS + c];
                af[mt][1] = As[st][(row + 8) * GAS + c];
                af[mt][2] = As[st][row * GAS + c + 4];
                af[mt][3] = As[st][(row + 8) * GAS + c + 4];
            }
            uint32_t bf[4][2];
#pragma unroll
            for (int nt = 0; nt < 4; nt++) {
                int n = warp_n + nt * 8 + (lane >> 2);
                bf[nt][0] = Bs[st][n * GAS + c];
                bf[nt][1] = Bs[st][n * GAS + c + 4];
            }
#pragma unroll
            for (int mt = 0; mt < 4; mt++)
#pragma unroll
                for (int nt = 0; nt < 4; nt++)
                    mma8(acc[mt][nt][0], acc[mt][nt][1], acc[mt][nt][2], acc[mt][nt][3],
                         af[mt][0], af[mt][1], af[mt][2], af[mt][3],
                         bf[nt][0], bf[nt][1]);
        }
        __syncthreads();
    }

#pragma unroll
    for (int mt = 0; mt < 4; mt++) {
        int row0 = bm + warp_m + mt * 16 + (lane >> 2);
#pragma unroll
        for (int nt = 0; nt < 4; nt++) {
            int col = bn + warp_n + nt * 8 + (lane & 3) * 2;
            float bb0 = bias[col], bb1 = bias[col + 1];
            float e00 = acc[mt][nt][0] + bb0, e01 = acc[mt][nt][1] + bb1;
            float e10 = acc[mt][nt][2] + bb0, e11 = acc[mt][nt][3] + bb1;
            if (round_out) {
                e00 = __uint_as_float(f2tf(e00));
                e01 = __uint_as_float(f2tf(e01));
                e10 = __uint_as_float(f2tf(e10));
                e11 = __uint_as_float(f2tf(e11));
            }
            if (row0 < M)
                *(float2*)(C + (size_t)row0 * N + col) = make_float2(e00, e01);
            if (row0 + 8 < M)
                *(float2*)(C + (size_t)(row0 + 8) * N + col) = make_float2(e10, e11);
        }
    }
}

// ---------------------------------------------------------------------------
// Fused RMSNorm + 3D RoPE (angles fp64, first principles), tf32-rounded store.
// ---------------------------------------------------------------------------
__global__ __launch_bounds__(256) void rmsrope_kernel(
    float* __restrict__ q, float* __restrict__ k,
    const float* __restrict__ gq, const float* __restrict__ gk)
{
    const int s = blockIdx.x;
    const int tid = threadIdx.x;
    float* qr = q + (size_t)s * DIM;
    float* kr = k + (size_t)s * DIM;

    float sq = 0.f, sk = 0.f;
    for (int i = tid; i < DIM; i += 256) {
        float a = qr[i]; sq = fmaf(a, a, sq);
        float b = kr[i]; sk = fmaf(b, b, sk);
    }
    __shared__ float bq_[256], bk_[256];
    bq_[tid] = sq; bk_[tid] = sk;
    __syncthreads();
    for (int off = 128; off > 0; off >>= 1) {
        if (tid < off) { bq_[tid] += bq_[tid + off]; bk_[tid] += bk_[tid + off]; }
        __syncthreads();
    }
    const float rq = rsqrtf(bq_[0] * (1.0f / DIM) + EPSN);
    const float rk = rsqrtf(bk_[0] * (1.0f / DIM) + EPSN);

    const int f = s / (HH * WW);
    const int rem = s - f * (HH * WW);
    const int hp = rem / WW;
    const int wp = rem - hp * WW;

#pragma unroll
    for (int u = 0; u < 3; u++) {
        int p = tid + u * 256;
        int h = p >> 6;
        int c = p & 63;
        int pos, j, dim;
        if (c < 22)      { pos = f;  j = c;      dim = 44; }
        else if (c < 43) { pos = hp; j = c - 22; dim = 42; }
        else             { pos = wp; j = c - 43; dim = 42; }
        double inv = pow(10000.0, -2.0 * (double)j / (double)dim);
        double ang = (double)pos * inv;
        double sd, cd;
        sincos(ang, &sd, &cd);
        float cs = (float)cd, sn = (float)sd;

        int base = h * HD + 2 * c;
        float q0 = qr[base] * rq * gq[base];
        float q1 = qr[base + 1] * rq * gq[base + 1];
        qr[base]     = __uint_as_float(f2tf(q0 * cs - q1 * sn));
        qr[base + 1] = __uint_as_float(f2tf(q0 * sn + q1 * cs));
        float k0 = kr[base] * rk * gk[base];
        float k1 = kr[base + 1] * rk * gk[base + 1];
        kr[base]     = __uint_as_float(f2tf(k0 * cs - k1 * sn));
        kr[base + 1] = __uint_as_float(f2tf(k0 * sn + k1 * cs));
    }
}

// ---------------------------------------------------------------------------
// Flash attention, tf32 mma. 64 q-rows per block, 256 threads, 2 blocks/SM.
// K and V share one smem tile (K for S-phase, V overwrites for O-phase).
// Inputs q/k/v are pre-rounded tf32 bits -> no converts here.
// ---------------------------------------------------------------------------
#define QT 64
#define QKS 132
#define PSS 68
#define FL_SMEM_U32 (2 * QT * QKS + QT * PSS + 3 * QT)
#define FL_SMEM_BYTES (FL_SMEM_U32 * 4)

__global__ __launch_bounds__(256, 2) void flash_tf32(
    const float* __restrict__ q, const float* __restrict__ k,
    const float* __restrict__ v, float* __restrict__ o,
    const int* __restrict__ seq_lens)
{
    extern __shared__ uint32_t smu[];
    uint32_t* Qs  = smu;                     // [64][QKS]
    uint32_t* KVs = Qs + QT * QKS;           // [64][QKS]  K then V
    float* Ps   = (float*)(KVs + QT * QKS);  // [64][PSS]
    float* mrow = Ps + QT * PSS;
    float* lrow = mrow + QT;
    float* arow = lrow + QT;

    const int tid = threadIdx.x;
    const int lane = tid & 31;
    const int wid = tid >> 5;
    const int head = blockIdx.y;
    const int q0 = blockIdx.x * QT;
    const int seqlen = seq_lens[0];
    const int hoff = head * HD;

    const int wm_s = (wid >> 2) * 32;
    const int wn_s = (wid & 3) * 16;
    const int wm_o = (wid >> 2) * 32;
    const int wn_o = (wid & 3) * 32;

    // load Q tile (already tf32-rounded bits)
#pragma unroll
    for (int u = 0; u < 8; u++) {
        int slot = tid + 256 * u;
        int r = slot >> 5;
        int qq = (slot & 31) * 4;
        int grow = q0 + r;
        float4 val = (grow < S_LEN) ? *(const float4*)(q + (size_t)grow * DIM + hoff + qq)
                                    : make_float4(0.f, 0.f, 0.f, 0.f);
        Qs[r * QKS + qq + 0] = __float_as_uint(val.x);
        Qs[r * QKS + qq + 1] = __float_as_uint(val.y);
        Qs[r * QKS + qq + 2] = __float_as_uint(val.z);
        Qs[r * QKS + qq + 3] = __float_as_uint(val.w);
    }
    if (tid < QT) { mrow[tid] = -3.0e38f; lrow[tid] = 0.f; }

    float oacc[2][4][4];
#pragma unroll
    for (int a = 0; a < 2; a++)
#pragma unroll
        for (int b = 0; b < 4; b++)
#pragma unroll
            for (int c = 0; c < 4; c++) oacc[a][b][c] = 0.f;

    const float scale = 0.08838834764831845f;

    const int ldr = tid >> 5;           // kv row base for this thread's slots
    const int ldq = (tid & 31) * 4;

    // prefetch K chunk 0
    float4 kvreg[8];
#pragma unroll
    for (int u = 0; u < 8; u++) {
        int r = ldr + u * 8;
        kvreg[u] = (r < seqlen) ? *(const float4*)(k + (size_t)r * DIM + hoff + ldq)
                                : make_float4(0.f, 0.f, 0.f, 0.f);
    }

    for (int kv0 = 0; kv0 < seqlen; kv0 += 64) {
        __syncthreads();   // prev O-phase done reading KVs
        // store K chunk
#pragma unroll
        for (int u = 0; u < 8; u++) {
            int r = ldr + u * 8;
            KVs[r * QKS + ldq + 0] = __float_as_uint(kvreg[u].x);
            KVs[r * QKS + ldq + 1] = __float_as_uint(kvreg[u].y);
            KVs[r * QKS + ldq + 2] = __float_as_uint(kvreg[u].z);
            KVs[r * QKS + ldq + 3] = __float_as_uint(kvreg[u].w);
        }
        __syncthreads();

        // prefetch V chunk (overlaps S-phase mma)
#pragma unroll
        for (int u = 0; u < 8; u++) {
            int r = kv0 + ldr + u * 8;
            kvreg[u] = (r < seqlen) ? *(const float4*)(v + (size_t)r * DIM + hoff + ldq)
                                    : make_float4(0.f, 0.f, 0.f, 0.f);
        }

        // ---------- S = Q @ K^T : 64x64, per-warp 32x16 ----------
        float sacc[2][2][4];
#pragma unroll
        for (int a = 0; a < 2; a++)
#pragma unroll
            for (int b = 0; b < 2; b++)
#pragma unroll
                for (int c = 0; c < 4; c++) sacc[a][b][c] = 0.f;

#pragma unroll
        for (int ks = 0; ks < 16; ks++) {
            const int c = ks * 8 + (lane & 3);
            uint32_t af[2][4];
#pragma unroll
            for (int mt = 0; mt < 2; mt++) {
                int row = wm_s + mt * 16 + (lane >> 2);
                af[mt][0] = Qs[row * QKS + c];
                af[mt][1] = Qs[(row + 8) * QKS + c];
                af[mt][2] = Qs[row * QKS + c + 4];
                af[mt][3] = Qs[(row + 8) * QKS + c + 4];
            }
            uint32_t bf[2][2];
#pragma unroll
            for (int nt = 0; nt < 2; nt++) {
                int n = wn_s + nt * 8 + (lane >> 2);
                bf[nt][0] = KVs[n * QKS + c];
                bf[nt][1] = KVs[n * QKS + c + 4];
            }
#pragma unroll
            for (int mt = 0; mt < 2; mt++)
#pragma unroll
                for (int nt = 0; nt < 2; nt++)
                    mma8(sacc[mt][nt][0], sacc[mt][nt][1], sacc[mt][nt][2], sacc[mt][nt][3],
                         af[mt][0], af[mt][1], af[mt][2], af[mt][3],
                         bf[nt][0], bf[nt][1]);
        }

        // write scaled+masked scores
#pragma unroll
        for (int mt = 0; mt < 2; mt++) {
            int row = wm_s + mt * 16 + (lane >> 2);
#pragma unroll
            for (int nt = 0; nt < 2; nt++) {
                int col = wn_s + nt * 8 + (lane & 3) * 2;
                bool m0 = (kv0 + col) >= seqlen;
                bool m1 = (kv0 + col + 1) >= seqlen;
                float2 v0 = make_float2(m0 ? -1e30f : sacc[mt][nt][0] * scale,
                                        m1 ? -1e30f : sacc[mt][nt][1] * scale);
                float2 v1 = make_float2(m0 ? -1e30f : sacc[mt][nt][2] * scale,
                                        m1 ? -1e30f : sacc[mt][nt][3] * scale);
                *(float2*)(Ps + row * PSS + col) = v0;
                *(float2*)(Ps + (row + 8) * PSS + col) = v1;
            }
        }
        __syncthreads();   // S-phase KVs reads done; P visible

        // store V chunk over K (scoreboard waits on vreg loads)
#pragma unroll
        for (int u = 0; u < 8; u++) {
            int r = ldr + u * 8;
            KVs[r * QKS + ldq + 0] = __float_as_uint(kvreg[u].x);
            KVs[r * QKS + ldq + 1] = __float_as_uint(kvreg[u].y);
            KVs[r * QKS + ldq + 2] = __float_as_uint(kvreg[u].z);
            KVs[r * QKS + ldq + 3] = __float_as_uint(kvreg[u].w);
        }

        // prefetch next K chunk (overlaps softmax + O-phase)
        if (kv0 + 64 < seqlen) {
#pragma unroll
            for (int u = 0; u < 8; u++) {
                int r = kv0 + 64 + ldr + u * 8;
                kvreg[u] = (r < seqlen) ? *(const float4*)(k + (size_t)r * DIM + hoff + ldq)
                                        : make_float4(0.f, 0.f, 0.f, 0.f);
            }
        }

        // ---------- online softmax (4 threads per row) ----------
        {
            const int i = tid >> 2, sub = tid & 3;
            const int jbase = sub * 16;
            float mold = mrow[i];
            float mloc = -3.0e38f;
#pragma unroll
            for (int jj = 0; jj < 16; jj++)
                mloc = fmaxf(mloc, Ps[i * PSS + jbase + jj]);
            mloc = fmaxf(mloc, __shfl_xor_sync(0xffffffffu, mloc, 1));
            mloc = fmaxf(mloc, __shfl_xor_sync(0xffffffffu, mloc, 2));
            float mnew = fmaxf(mold, mloc);
            float sum = 0.f;
#pragma unroll
            for (int jj = 0; jj < 16; jj++) {
                float p = __expf(Ps[i * PSS + jbase + jj] - mnew);
                Ps[i * PSS + jbase + jj] = p;
                sum += p;
            }
            sum += __shfl_xor_sync(0xffffffffu, sum, 1);
            sum += __shfl_xor_sync(0xffffffffu, sum, 2);
            if (sub == 0) {
                float al = __expf(mold - mnew);
                arow[i] = al;
                lrow[i] = lrow[i] * al + sum;
                mrow[i] = mnew;
            }
        }
        __syncthreads();   // V stores + softmax P updates visible

        // ---------- O = alpha*O + P @ V : per-warp 32x32 ----------
#pragma unroll
        for (int mt = 0; mt < 2; mt++) {
            int row = wm_o + mt * 16 + (lane >> 2);
            float al0 = arow[row];
            float al1 = arow[row + 8];
#pragma unroll
            for (int nt = 0; nt < 4; nt++) {
                oacc[mt][nt][0] *= al0;
                oacc[mt][nt][1] *= al0;
                oacc[mt][nt][2] *= al1;
                oacc[mt][nt][3] *= al1;
            }
        }
#pragma unroll
        for (int ks = 0; ks < 8; ks++) {
            const int c = ks * 8 + (lane & 3);
            uint32_t paf[2][4];
#pragma unroll
            for (int mt = 0; mt < 2; mt++) {
                int row = wm_o + mt * 16 + (lane >> 2);
                paf[mt][0] = __float_as_uint(Ps[row * PSS + c]);
                paf[mt][1] = __float_as_uint(Ps[(row + 8) * PSS + c]);
                paf[mt][2] = __float_as_uint(Ps[row * PSS + c + 4]);
                paf[mt][3] = __float_as_uint(Ps[(row + 8) * PSS + c + 4]);
            }
#pragma unroll
            for (int nt = 0; nt < 4; nt++) {
                int n = wn_o + nt * 8 + (lane >> 2);
                uint32_t b0 = KVs[c * QKS + n];
                uint32_t b1 = KVs[(c + 4) * QKS + n];
#pragma unroll
                for (int mt = 0; mt < 2; mt++)
                    mma8(oacc[mt][nt][0], oacc[mt][nt][1], oacc[mt][nt][2], oacc[mt][nt][3],
                         paf[mt][0], paf[mt][1], paf[mt][2], paf[mt][3], b0, b1);
            }
        }
    }

    // epilogue: divide by l, tf32-round (o feeds the tf32 O-projection), store
#pragma unroll
    for (int mt = 0; mt < 2; mt++) {
        int lrow0 = wm_o + mt * 16 + (lane >> 2);
        int grow0 = q0 + lrow0;
        float inv0 = 1.0f / lrow[lrow0];
        float inv1 = 1.0f / lrow[lrow0 + 8];
#pragma unroll
        for (int nt = 0; nt < 4; nt++) {
            int col = hoff + wn_o + nt * 8 + (lane & 3) * 2;
            if (grow0 < S_LEN) {
                float2 v0 = make_float2(
                    __uint_as_float(f2tf(oacc[mt][nt][0] * inv0)),
                    __uint_as_float(f2tf(oacc[mt][nt][1] * inv0)));
                *(float2*)(o + (size_t)grow0 * DIM + col) = v0;
            }
            if (grow0 + 8 < S_LEN) {
                float2 v1 = make_float2(
                    __uint_as_float(f2tf(oacc[mt][nt][2] * inv1)),
                    __uint_as_float(f2tf(oacc[mt][nt][3] * inv1)));
                *(float2*)(o + (size_t)(grow0 + 8) * DIM + col) = v1;
            }
        }
    }
}

// ---------------------------------------------------------------------------
extern "C" void kernel_launch(void* const* d_in, const int* in_sizes, int n_in,
                              void* d_out, int out_size)
{
    const float* x  = (const float*)d_in[0];
    const float* wq = (const float*)d_in[1];
    const float* bq = (const float*)d_in[2];
    const float* wk = (const float*)d_in[3];
    const float* bk = (const float*)d_in[4];
    const float* wv = (const float*)d_in[5];
    const float* bv = (const float*)d_in[6];
    const float* wo = (const float*)d_in[7];
    const float* bo = (const float*)d_in[8];
    const float* gq = (const float*)d_in[9];
    const float* gk = (const float*)d_in[10];
    const int* seq_lens = (const int*)d_in[12];
    float* out = (float*)d_out;

    float *qp, *kp, *vp, *op, *xp, *wqp, *wkp, *wvp, *wop;
    cudaGetSymbolAddress((void**)&qp, g_q);
    cudaGetSymbolAddress((void**)&kp, g_k);
    cudaGetSymbolAddress((void**)&vp, g_v);
    cudaGetSymbolAddress((void**)&op, g_o);
    cudaGetSymbolAddress((void**)&xp, g_x);
    cudaGetSymbolAddress((void**)&wqp, g_wq);
    cudaGetSymbolAddress((void**)&wkp, g_wk);
    cudaGetSymbolAddress((void**)&wvp, g_wv);
    cudaGetSymbolAddress((void**)&wop, g_wo);

    // pre-round inputs to tf32 (rna)
    const int nx4 = S_LEN * DIM / 4;
    const int nw4 = DIM * DIM / 4;
    pre_round<<<(nx4 + 255) / 256, 256>>>(x, xp, nx4);
    pre_round<<<(nw4 + 255) / 256, 256>>>(wq, wqp, nw4);
    pre_round<<<(nw4 + 255) / 256, 256>>>(wk, wkp, nw4);
    pre_round<<<(nw4 + 255) / 256, 256>>>(wv, wvp, nw4);
    pre_round<<<(nw4 + 255) / 256, 256>>>(wo, wop, nw4);

    // fused Q/K/V projections (rounded tf32 outputs)
    dim3 gqkv(DIM / 128, (S_LEN + 127) / 128, 3);
    gemm_nt_tf32<<<gqkv, 256>>>(xp, wqp, wkp, wvp, bq, bk, bv, qp, kp, vp,
                                S_LEN, DIM, DIM, 1);

    rmsrope_kernel<<<S_LEN, 256>>>(qp, kp, gq, gk);

    cudaFuncSetAttribute(flash_tf32, cudaFuncAttributeMaxDynamicSharedMemorySize,
                         FL_SMEM_BYTES);
    flash_tf32<<<dim3((S_LEN + QT - 1) / QT, NH), 256, FL_SMEM_BYTES>>>(
        qp, kp, vp, op, seq_lens);

    // output projection (fp32 output, no rounding)
    dim3 go(DIM / 128, (S_LEN + 127) / 128, 1);
    gemm_nt_tf32<<<go, 256>>>(op, wop, wop, wop, bo, bo, bo, out, out, out,
                              S_LEN, DIM, DIM, 0);
}